// round 9
// baseline (speedup 1.0000x reference)
#include <cuda_runtime.h>
#include <cstdint>
#include <cstddef>

#define BB 8
#define TT 128
#define SS 512
#define DD 128
#define CL 8           // cluster size (CTAs per batch)
#define ROWS 64        // SS/CL encoder rows per CTA
#define NTH 512
#define COLS_PER 16    // DD/CL output columns per CTA

// scratch (static device globals -- no allocation)
__device__ float g_HU[BB * SS * DD];          // H @ Ua
__device__ float g_XW4[BB * TT * 4 * DD];     // x @ {Wi,Wf,Wc,Wo} + bias

// ---------------------------------------------------------------- helpers
__device__ __forceinline__ uint32_t s2u(const void* p) {
    uint32_t a;
    asm("{ .reg .u64 t; cvta.to.shared.u64 t, %1; cvt.u32.u64 %0, t; }"
        : "=r"(a) : "l"(p));
    return a;
}
__device__ __forceinline__ void st_rank(uint32_t laddr, uint32_t rank, float v) {
    uint32_t r;
    asm("mapa.shared::cluster.u32 %0, %1, %2;" : "=r"(r) : "r"(laddr), "r"(rank));
    asm volatile("st.shared::cluster.f32 [%0], %1;" :: "r"(r), "f"(v) : "memory");
}
#define CLUSTER_SYNC() do { \
    asm volatile("barrier.cluster.arrive.aligned;" ::: "memory"); \
    asm volatile("barrier.cluster.wait.aligned;"   ::: "memory"); \
} while (0)

// MUFU tanh for the attention score path (softmax weights only; ~5e-4 abs err)
__device__ __forceinline__ float tanh_mufu(float x) {
    float y;
    asm("tanh.approx.f32 %0, %1;" : "=f"(y) : "f"(x));
    return y;
}
// accurate activations for the LSTM gates (recurrent state path)
__device__ __forceinline__ float sigmoid_acc(float x) {
    return __fdividef(1.0f, 1.0f + __expf(-x));
}
__device__ __forceinline__ float tanh_acc(float x) {
    float e = __expf(2.0f * x);
    return __fdividef(e - 1.0f, e + 1.0f);
}

// ---------------------------------------------------------------- precompute
// HU[b,s,:] = H[b,s,:] @ Ua      (16 rows per block, deep-MLP k loop)
__global__ void __launch_bounds__(DD) hu_kernel(const float* __restrict__ Hm,
                                                const float* __restrict__ Ua) {
    __shared__ float hrow[16][DD];
    int r0 = blockIdx.x * 16;
    int d = threadIdx.x;
    #pragma unroll
    for (int i = 0; i < 16; i++) hrow[i][d] = Hm[(size_t)(r0 + i) * DD + d];
    __syncthreads();
    float acc[16];
    #pragma unroll
    for (int i = 0; i < 16; i++) acc[i] = 0.0f;
    #pragma unroll 16
    for (int k = 0; k < DD; k++) {
        float u = Ua[k * DD + d];
        #pragma unroll
        for (int i = 0; i < 16; i++) acc[i] = fmaf(hrow[i][k], u, acc[i]);
    }
    #pragma unroll
    for (int i = 0; i < 16; i++) g_HU[(size_t)(r0 + i) * DD + d] = acc[i];
}

// XW4[row,g,:] = x[row,:] @ W_g + b_g   (8 rows per block)
__global__ void __launch_bounds__(DD) xw_kernel(const float* __restrict__ x,
    const float* __restrict__ Wi_, const float* __restrict__ Wf_,
    const float* __restrict__ Wc_, const float* __restrict__ Wo_,
    const float* __restrict__ bi_, const float* __restrict__ bf_,
    const float* __restrict__ bc_, const float* __restrict__ bo_) {
    __shared__ float xr[8][DD];
    int r0 = blockIdx.x * 8;
    int d = threadIdx.x;
    #pragma unroll
    for (int i = 0; i < 8; i++) xr[i][d] = x[(size_t)(r0 + i) * DD + d];
    __syncthreads();
    const float* Ws[4] = {Wi_, Wf_, Wc_, Wo_};
    const float* bs[4] = {bi_, bf_, bc_, bo_};
    #pragma unroll
    for (int g = 0; g < 4; g++) {
        float bb = bs[g][d];
        float acc[8];
        #pragma unroll
        for (int i = 0; i < 8; i++) acc[i] = bb;
        #pragma unroll 16
        for (int k = 0; k < DD; k++) {
            float w = Ws[g][k * DD + d];
            #pragma unroll
            for (int i = 0; i < 8; i++) acc[i] = fmaf(xr[i][k], w, acc[i]);
        }
        #pragma unroll
        for (int i = 0; i < 8; i++)
            g_XW4[(((size_t)(r0 + i)) * 4 + g) * DD + d] = acc[i];
    }
}

// ---------------------------------------------------------------- main persistent kernel
// grid (CL, BB): cluster of CL CTAs along x per batch (blockIdx.y).
__global__ void __launch_bounds__(NTH, 1) __cluster_dims__(CL, 1, 1)
attn_lstm_kernel(const float* __restrict__ H, const float* __restrict__ init_states,
                 const float* __restrict__ Wa, const float* __restrict__ v,
                 const float* __restrict__ Ui, const float* __restrict__ Uf,
                 const float* __restrict__ Uc, const float* __restrict__ Uo,
                 const float* __restrict__ Ci, const float* __restrict__ Cf,
                 const float* __restrict__ Cc, const float* __restrict__ Co,
                 float* __restrict__ out)
{
    __shared__ float Wa_s[COLS_PER][DD];              // Wa rows [16r, 16r+16)
    __shared__ alignas(16) float v_s[DD];
    __shared__ alignas(16) float hbuf[2][DD];
    __shared__ alignas(16) float q_s[DD];
    __shared__ float qpart[CL][DD];
    __shared__ alignas(16) float ctx_s[DD];
    __shared__ float ctxpart[CL][DD + 4];             // [.., DD] = partial exp-sum
    __shared__ alignas(16) float wred[16][DD];
    __shared__ float wsum[16];
    __shared__ float gate_sm[4][COLS_PER];
    __shared__ float hn[COLS_PER];

    const int tid  = threadIdx.x;
    const int b    = blockIdx.y;
    uint32_t rank;
    asm("mov.u32 %0, %%cluster_ctarank;" : "=r"(rank));
    const int j    = tid & 7;
    const int sl   = tid >> 3;           // encoder-row-local index in phase 2
    const int warp = tid >> 5;
    const int lane = tid & 31;

    const int g   = sl >> 4;             // gate 0..3  (i, f, c~, o)
    const int cl_ = sl & 15;             // local column
    const int col = (int)rank * COLS_PER + cl_;

    // ---- persistent register tiles (contiguous k-layout: k = 16*j + m) ----
    float HUr[16], Hr[16], Ur[16], Cr[16];
    {
        const int srow = (int)rank * ROWS + sl;
        const float* hu = g_HU + ((size_t)b * SS + srow) * DD;
        const float* hp = H    + ((size_t)b * SS + srow) * DD;
        #pragma unroll
        for (int m = 0; m < 16; m++) { int d = 16 * j + m; HUr[m] = hu[d]; Hr[m] = hp[d]; }
        const float* Ug = (g == 0) ? Ui : (g == 1) ? Uf : (g == 2) ? Uc : Uo;
        const float* Cg = (g == 0) ? Ci : (g == 1) ? Cf : (g == 2) ? Cc : Co;
        #pragma unroll
        for (int m = 0; m < 16; m++) { int k = 16 * j + m; Ur[m] = Ug[k * DD + col]; Cr[m] = Cg[k * DD + col]; }
    }
    // c state is private to its owning thread: keep it in a register
    float creg = (tid < COLS_PER)
               ? init_states[(BB + b) * DD + (int)rank * COLS_PER + tid] : 0.0f;

    // ---- smem init ----
    for (int i = tid; i < COLS_PER * DD; i += NTH) {
        int kr = i >> 7, dd = i & 127;
        Wa_s[kr][dd] = Wa[((int)rank * COLS_PER + kr) * DD + dd];
    }
    if (tid < DD) {
        v_s[tid]     = v[tid];
        hbuf[0][tid] = init_states[b * DD + tid];
    }
    __syncthreads();
    // initial q partial from h0's k-slice, broadcast to all CTAs (incl. self)
    if (tid < DD) {
        float acc = 0.0f;
        #pragma unroll
        for (int k = 0; k < COLS_PER; k++)
            acc = fmaf(hbuf[0][(int)rank * COLS_PER + k], Wa_s[k][tid], acc);
        uint32_t la = s2u(&qpart[rank][tid]);
        #pragma unroll
        for (uint32_t rr = 0; rr < CL; rr++) st_rank(la, rr, acc);
    }

    const float* xw_base = g_XW4 + (size_t)b * TT * 4 * DD;

    for (int t = 0; t < TT; t++) {
        const int p = t & 1;
        CLUSTER_SYNC();                   // qpart(t) + hbuf[p] from all peers visible

        // prefetch the x@W gate term early (L2 latency hidden behind phase 2)
        float xwv = (j == 0) ? xw_base[((size_t)t * 4 + g) * DD + col] : 0.0f;

        // ---- build full q ----
        if (tid < DD) {
            float acc = qpart[0][tid];
            #pragma unroll
            for (int rr = 1; rr < CL; rr++) acc += qpart[rr][tid];
            q_s[tid] = acc;
        }
        __syncthreads();

        // ---- phase 2: scores (MUFU tanh) + exp + local context partial ----
        {
            float qv[16], vv[16];
            const float4* q4 = (const float4*)&q_s[16 * j];
            const float4* v4 = (const float4*)&v_s[16 * j];
            #pragma unroll
            for (int mm = 0; mm < 4; mm++) {
                float4 a = q4[mm];
                qv[4*mm] = a.x; qv[4*mm+1] = a.y; qv[4*mm+2] = a.z; qv[4*mm+3] = a.w;
                float4 bv = v4[mm];
                vv[4*mm] = bv.x; vv[4*mm+1] = bv.y; vv[4*mm+2] = bv.z; vv[4*mm+3] = bv.w;
            }
            float acc = 0.0f;
            #pragma unroll
            for (int m = 0; m < 16; m++)
                acc = fmaf(tanh_mufu(HUr[m] + qv[m]), vv[m], acc);
            acc += __shfl_xor_sync(0xffffffffu, acc, 1);
            acc += __shfl_xor_sync(0xffffffffu, acc, 2);
            acc += __shfl_xor_sync(0xffffffffu, acc, 4);
            float e = __expf(acc);        // scores are tiny; no max-shift needed
            float cp[16];
            #pragma unroll
            for (int m = 0; m < 16; m++) cp[m] = e * Hr[m];
            #pragma unroll
            for (int m = 0; m < 16; m++) {   // reduce over the 4 rows in this warp
                cp[m] += __shfl_xor_sync(0xffffffffu, cp[m], 8);
                cp[m] += __shfl_xor_sync(0xffffffffu, cp[m], 16);
            }
            float es = e + __shfl_xor_sync(0xffffffffu, e, 8);
            es += __shfl_xor_sync(0xffffffffu, es, 16);
            if (lane < 8) {
                float4* w4 = (float4*)&wred[warp][16 * lane];
                #pragma unroll
                for (int mm = 0; mm < 4; mm++)
                    w4[mm] = make_float4(cp[4*mm], cp[4*mm+1], cp[4*mm+2], cp[4*mm+3]);
                if (lane == 0) wsum[warp] = es;
            }
        }
        __syncthreads();
        // local reduce over 16 warps, broadcast (ctx partial + exp-sum) to all CTAs
        if (tid < DD) {
            float acc = wred[0][tid];
            #pragma unroll
            for (int w = 1; w < 16; w++) acc += wred[w][tid];
            uint32_t la = s2u(&ctxpart[rank][tid]);
            #pragma unroll
            for (uint32_t rr = 0; rr < CL; rr++) st_rank(la, rr, acc);
            if (tid == 0) {
                float es = wsum[0];
                #pragma unroll
                for (int w = 1; w < 16; w++) es += wsum[w];
                uint32_t lb = s2u(&ctxpart[rank][DD]);
                #pragma unroll
                for (uint32_t rr = 0; rr < CL; rr++) st_rank(lb, rr, es);
            }
        }
        CLUSTER_SYNC();                   // ctx partials from all peers visible

        // ---- phase 3: full context, gates, state update ----
        if (tid < DD) {
            float acc = ctxpart[0][tid];
            float es  = ctxpart[0][DD];
            #pragma unroll
            for (int rr = 1; rr < CL; rr++) { acc += ctxpart[rr][tid]; es += ctxpart[rr][DD]; }
            ctx_s[tid] = acc * __fdividef(1.0f, es);
        }
        __syncthreads();
        {
            float hk[16], ck[16];
            const float4* h4 = (const float4*)&hbuf[p][16 * j];
            const float4* c4 = (const float4*)&ctx_s[16 * j];
            #pragma unroll
            for (int mm = 0; mm < 4; mm++) {
                float4 a = h4[mm];
                hk[4*mm] = a.x; hk[4*mm+1] = a.y; hk[4*mm+2] = a.z; hk[4*mm+3] = a.w;
                float4 bv = c4[mm];
                ck[4*mm] = bv.x; ck[4*mm+1] = bv.y; ck[4*mm+2] = bv.z; ck[4*mm+3] = bv.w;
            }
            float acc = 0.0f;
            #pragma unroll
            for (int m = 0; m < 16; m++) {
                acc = fmaf(hk[m], Ur[m], acc);
                acc = fmaf(ck[m], Cr[m], acc);
            }
            acc += __shfl_xor_sync(0xffffffffu, acc, 1);
            acc += __shfl_xor_sync(0xffffffffu, acc, 2);
            acc += __shfl_xor_sync(0xffffffffu, acc, 4);
            if (j == 0) {
                float pre = acc + xwv;
                gate_sm[g][cl_] = (g == 2) ? tanh_acc(pre) : sigmoid_acc(pre);
            }
        }
        __syncthreads();
        if (tid < COLS_PER) {
            float ig = gate_sm[0][tid], fg = gate_sm[1][tid];
            float gg = gate_sm[2][tid], og = gate_sm[3][tid];
            int colw = (int)rank * COLS_PER + tid;
            float cnew = fmaf(fg, creg, ig * gg);
            creg = cnew;
            float hnew = og * tanh_acc(cnew);
            hn[tid] = hnew;
            out[((size_t)b * TT + t) * DD + colw] = hnew;
            if (t < TT - 1) {
                uint32_t lah = s2u(&hbuf[p ^ 1][colw]);
                #pragma unroll
                for (uint32_t rr = 0; rr < CL; rr++) st_rank(lah, rr, hnew);
            }
        }
        __syncthreads();
        // next-step q partial from this CTA's h-slice
        if (tid < DD && t < TT - 1) {
            float acc = 0.0f;
            #pragma unroll
            for (int k = 0; k < COLS_PER; k++) acc = fmaf(hn[k], Wa_s[k][tid], acc);
            uint32_t la = s2u(&qpart[rank][tid]);
            #pragma unroll
            for (uint32_t rr = 0; rr < CL; rr++) st_rank(la, rr, acc);
        }
    }
    CLUSTER_SYNC();                       // no CTA exits with peer DSMEM traffic in flight
}

// ---------------------------------------------------------------- launch
extern "C" void kernel_launch(void* const* d_in, const int* in_sizes, int n_in,
                              void* d_out, int out_size) {
    (void)in_sizes; (void)n_in; (void)out_size;
    const float* x    = (const float*)d_in[0];
    const float* H    = (const float*)d_in[1];
    const float* init = (const float*)d_in[2];
    const float* Wa   = (const float*)d_in[3];
    const float* Ua   = (const float*)d_in[4];
    const float* v    = (const float*)d_in[5];
    const float* Wi   = (const float*)d_in[6];
    const float* Ui   = (const float*)d_in[7];
    const float* Ci   = (const float*)d_in[8];
    const float* bi   = (const float*)d_in[9];
    const float* Wf   = (const float*)d_in[10];
    const float* Uf   = (const float*)d_in[11];
    const float* Cf   = (const float*)d_in[12];
    const float* bf   = (const float*)d_in[13];
    const float* Wc   = (const float*)d_in[14];
    const float* Uc   = (const float*)d_in[15];
    const float* Cc   = (const float*)d_in[16];
    const float* bc   = (const float*)d_in[17];
    const float* Wo   = (const float*)d_in[18];
    const float* Uo   = (const float*)d_in[19];
    const float* Co   = (const float*)d_in[20];
    const float* bo   = (const float*)d_in[21];
    float* out = (float*)d_out;

    hu_kernel<<<(BB * SS) / 16, DD>>>(H, Ua);
    xw_kernel<<<(BB * TT) / 8, DD>>>(x, Wi, Wf, Wc, Wo, bi, bf, bc, bo);
    attn_lstm_kernel<<<dim3(CL, BB), NTH>>>(H, init, Wa, v,
                                            Ui, Uf, Uc, Uo, Ci, Cf, Cc, Co, out);
}

// round 10
// speedup vs baseline: 1.4444x; 1.4444x over previous
#include <cuda_runtime.h>
#include <cstdint>
#include <cstddef>

#define BB 8
#define TT 128
#define SS 512
#define DD 128
#define CL 8           // cluster size (CTAs per batch)
#define ROWS 64        // SS/CL encoder rows per CTA
#define NTH 512
#define COLS_PER 16    // DD/CL output columns per CTA

// scratch (static device globals -- no allocation)
__device__ float g_HU[BB * SS * DD];          // H @ Ua
__device__ float g_XW4[BB * TT * 4 * DD];     // x @ {Wi,Wf,Wc,Wo} + bias

// ---------------------------------------------------------------- helpers
__device__ __forceinline__ uint32_t s2u(const void* p) {
    uint32_t a;
    asm("{ .reg .u64 t; cvta.to.shared.u64 t, %1; cvt.u32.u64 %0, t; }"
        : "=r"(a) : "l"(p));
    return a;
}
__device__ __forceinline__ void st_rank(uint32_t laddr, uint32_t rank, float v) {
    uint32_t r;
    asm("mapa.shared::cluster.u32 %0, %1, %2;" : "=r"(r) : "r"(laddr), "r"(rank));
    asm volatile("st.shared::cluster.f32 [%0], %1;" :: "r"(r), "f"(v) : "memory");
}
#define CLUSTER_SYNC() do { \
    asm volatile("barrier.cluster.arrive.aligned;" ::: "memory"); \
    asm volatile("barrier.cluster.wait.aligned;"   ::: "memory"); \
} while (0)

// MUFU tanh for the attention score path (feeds softmax weights only;
// ~5e-4 abs err, measured rel_err impact: none). Zero register pressure,
// runs on the otherwise-idle MUFU pipe instead of the binding FMA pipe.
__device__ __forceinline__ float tanh_mufu(float x) {
    float y;
    asm("tanh.approx.f32 %0, %1;" : "=f"(y) : "f"(x));
    return y;
}
// accurate activations for the LSTM gates (recurrent state path)
__device__ __forceinline__ float sigmoid_acc(float x) {
    return __fdividef(1.0f, 1.0f + __expf(-x));
}
__device__ __forceinline__ float tanh_acc(float x) {
    float e = __expf(2.0f * x);
    return __fdividef(e - 1.0f, e + 1.0f);
}

// ---------------------------------------------------------------- precompute
// HU[b,s,:] = H[b,s,:] @ Ua      (8 rows per block)
__global__ void __launch_bounds__(DD) hu_kernel(const float* __restrict__ Hm,
                                                const float* __restrict__ Ua) {
    __shared__ float hrow[8][DD];
    int r0 = blockIdx.x * 8;
    int d = threadIdx.x;
    #pragma unroll
    for (int i = 0; i < 8; i++) hrow[i][d] = Hm[(size_t)(r0 + i) * DD + d];
    __syncthreads();
    float acc[8];
    #pragma unroll
    for (int i = 0; i < 8; i++) acc[i] = 0.0f;
    #pragma unroll 4
    for (int k = 0; k < DD; k++) {
        float u = Ua[k * DD + d];
        #pragma unroll
        for (int i = 0; i < 8; i++) acc[i] = fmaf(hrow[i][k], u, acc[i]);
    }
    #pragma unroll
    for (int i = 0; i < 8; i++) g_HU[(size_t)(r0 + i) * DD + d] = acc[i];
}

// XW4[row,g,:] = x[row,:] @ W_g + b_g   (8 rows per block)
__global__ void __launch_bounds__(DD) xw_kernel(const float* __restrict__ x,
    const float* __restrict__ Wi_, const float* __restrict__ Wf_,
    const float* __restrict__ Wc_, const float* __restrict__ Wo_,
    const float* __restrict__ bi_, const float* __restrict__ bf_,
    const float* __restrict__ bc_, const float* __restrict__ bo_) {
    __shared__ float xr[8][DD];
    int r0 = blockIdx.x * 8;
    int d = threadIdx.x;
    #pragma unroll
    for (int i = 0; i < 8; i++) xr[i][d] = x[(size_t)(r0 + i) * DD + d];
    __syncthreads();
    const float* Ws[4] = {Wi_, Wf_, Wc_, Wo_};
    const float* bs[4] = {bi_, bf_, bc_, bo_};
    #pragma unroll
    for (int g = 0; g < 4; g++) {
        float bb = bs[g][d];
        float acc[8];
        #pragma unroll
        for (int i = 0; i < 8; i++) acc[i] = bb;
        #pragma unroll 4
        for (int k = 0; k < DD; k++) {
            float w = Ws[g][k * DD + d];
            #pragma unroll
            for (int i = 0; i < 8; i++) acc[i] = fmaf(xr[i][k], w, acc[i]);
        }
        #pragma unroll
        for (int i = 0; i < 8; i++)
            g_XW4[(((size_t)(r0 + i)) * 4 + g) * DD + d] = acc[i];
    }
}

// ---------------------------------------------------------------- main persistent kernel
// grid (CL, BB): cluster of CL CTAs along x per batch (blockIdx.y).
__global__ void __launch_bounds__(NTH, 1) __cluster_dims__(CL, 1, 1)
attn_lstm_kernel(const float* __restrict__ H, const float* __restrict__ init_states,
                 const float* __restrict__ Wa, const float* __restrict__ v,
                 const float* __restrict__ Ui, const float* __restrict__ Uf,
                 const float* __restrict__ Uc, const float* __restrict__ Uo,
                 const float* __restrict__ Ci, const float* __restrict__ Cf,
                 const float* __restrict__ Cc, const float* __restrict__ Co,
                 float* __restrict__ out)
{
    __shared__ float Wa_s[COLS_PER][DD];     // Wa rows [16r, 16r+16)
    __shared__ float v_s[DD];
    __shared__ float hbuf[2][DD], cbuf[2][DD];
    __shared__ float q_s[DD];
    __shared__ float qpart[CL][DD];
    __shared__ float ctx_s[DD];
    __shared__ float ctxpart[CL][DD + 4];    // [.., DD] = partial exp-sum
    __shared__ float wred[16][DD];
    __shared__ float wsum[16];
    __shared__ float gate_sm[4][COLS_PER];
    __shared__ float hn[COLS_PER], cn[COLS_PER];

    const int tid  = threadIdx.x;
    const int b    = blockIdx.y;
    uint32_t rank;
    asm("mov.u32 %0, %%cluster_ctarank;" : "=r"(rank));
    const int j    = tid & 7;
    const int sl   = tid >> 3;           // row-local (phase2) / pair index (phase3)
    const int warp = tid >> 5;
    const int lane = tid & 31;

    const int g   = sl >> 4;             // gate 0..3  (i, f, c~, o)
    const int cl_ = sl & 15;             // local column
    const int col = (int)rank * COLS_PER + cl_;

    // ---- persistent register tiles ----
    float HUr[16], Hr[16], Ur[16], Cr[16];
    {
        const int srow = (int)rank * ROWS + sl;
        const float* hu = g_HU + ((size_t)b * SS + srow) * DD;
        const float* hp = H    + ((size_t)b * SS + srow) * DD;
        #pragma unroll
        for (int m = 0; m < 16; m++) { int d = j + 8 * m; HUr[m] = hu[d]; Hr[m] = hp[d]; }
        const float* Ug = (g == 0) ? Ui : (g == 1) ? Uf : (g == 2) ? Uc : Uo;
        const float* Cg = (g == 0) ? Ci : (g == 1) ? Cf : (g == 2) ? Cc : Co;
        #pragma unroll
        for (int m = 0; m < 16; m++) { int k = j + 8 * m; Ur[m] = Ug[k * DD + col]; Cr[m] = Cg[k * DD + col]; }
    }
    // ---- smem init ----
    for (int i = tid; i < COLS_PER * DD; i += NTH) {
        int kr = i >> 7, dd = i & 127;
        Wa_s[kr][dd] = Wa[((int)rank * COLS_PER + kr) * DD + dd];
    }
    if (tid < DD) {
        v_s[tid]     = v[tid];
        hbuf[0][tid] = init_states[b * DD + tid];
        cbuf[0][tid] = init_states[(BB + b) * DD + tid];
        hbuf[1][tid] = 0.0f; cbuf[1][tid] = 0.0f;
    }
    __syncthreads();
    // initial q partial from h0's k-slice, broadcast to all CTAs (incl. self)
    if (tid < DD) {
        float acc = 0.0f;
        #pragma unroll
        for (int k = 0; k < COLS_PER; k++)
            acc = fmaf(hbuf[0][(int)rank * COLS_PER + k], Wa_s[k][tid], acc);
        uint32_t la = s2u(&qpart[rank][tid]);
        #pragma unroll
        for (int rr = 0; rr < CL; rr++) st_rank(la, (uint32_t)rr, acc);
    }

    const float* xw_base = g_XW4 + (size_t)b * TT * 4 * DD;

    for (int t = 0; t < TT; t++) {
        const int p = t & 1;
        CLUSTER_SYNC();                      // qpart, hbuf[p], cbuf[p] from all peers visible

        // ---- build full q ----
        if (tid < DD) {
            float acc = qpart[0][tid];
            #pragma unroll
            for (int rr = 1; rr < CL; rr++) acc += qpart[rr][tid];
            q_s[tid] = acc;
        }
        __syncthreads();

        // ---- phase 2: scores + exp + local context partial for 64 rows ----
        {
            float acc = 0.0f;
            #pragma unroll
            for (int m = 0; m < 16; m++) {
                int d = j + 8 * m;
                float z = HUr[m] + q_s[d];
                acc = fmaf(tanh_mufu(z), v_s[d], acc);
            }
            acc += __shfl_xor_sync(0xffffffffu, acc, 1);
            acc += __shfl_xor_sync(0xffffffffu, acc, 2);
            acc += __shfl_xor_sync(0xffffffffu, acc, 4);
            float e = __expf(acc);           // scores are tiny; no max-shift needed
            float cp[16];
            #pragma unroll
            for (int m = 0; m < 16; m++) cp[m] = e * Hr[m];
            #pragma unroll
            for (int m = 0; m < 16; m++) {   // reduce over the 4 rows in this warp
                cp[m] += __shfl_xor_sync(0xffffffffu, cp[m], 8);
                cp[m] += __shfl_xor_sync(0xffffffffu, cp[m], 16);
            }
            float es = e + __shfl_xor_sync(0xffffffffu, e, 8);
            es += __shfl_xor_sync(0xffffffffu, es, 16);
            if (lane < 8) {
                #pragma unroll
                for (int m = 0; m < 16; m++) wred[warp][lane + 8 * m] = cp[m];
                if (lane == 0) wsum[warp] = es;
            }
        }
        __syncthreads();
        // local reduce over 16 warps, broadcast (ctx partial + exp-sum) to all CTAs
        if (tid < DD) {
            float acc = wred[0][tid];
            #pragma unroll
            for (int w = 1; w < 16; w++) acc += wred[w][tid];
            uint32_t la = s2u(&ctxpart[rank][tid]);
            #pragma unroll
            for (int rr = 0; rr < CL; rr++) st_rank(la, (uint32_t)rr, acc);
            if (tid == 0) {
                float es = wsum[0];
                #pragma unroll
                for (int w = 1; w < 16; w++) es += wsum[w];
                uint32_t lb = s2u(&ctxpart[rank][DD]);
                #pragma unroll
                for (int rr = 0; rr < CL; rr++) st_rank(lb, (uint32_t)rr, es);
            }
        }
        CLUSTER_SYNC();                      // ctx partials from all peers visible

        // ---- phase 3: full context, gates, state update ----
        if (tid < DD) {
            float acc = ctxpart[0][tid];
            float es  = ctxpart[0][DD];
            #pragma unroll
            for (int rr = 1; rr < CL; rr++) { acc += ctxpart[rr][tid]; es += ctxpart[rr][DD]; }
            ctx_s[tid] = acc * __fdividef(1.0f, es);
        }
        __syncthreads();
        {
            float acc = 0.0f;
            #pragma unroll
            for (int m = 0; m < 16; m++) {
                int k = j + 8 * m;
                acc = fmaf(hbuf[p][k], Ur[m], acc);
                acc = fmaf(ctx_s[k],  Cr[m], acc);
            }
            acc += __shfl_xor_sync(0xffffffffu, acc, 1);
            acc += __shfl_xor_sync(0xffffffffu, acc, 2);
            acc += __shfl_xor_sync(0xffffffffu, acc, 4);
            if (j == 0) {
                float pre = acc + xw_base[((size_t)t * 4 + g) * DD + col];
                gate_sm[g][cl_] = (g == 2) ? tanh_acc(pre) : sigmoid_acc(pre);
            }
        }
        __syncthreads();
        if (tid < COLS_PER) {
            float ig = gate_sm[0][tid], fg = gate_sm[1][tid];
            float gg = gate_sm[2][tid], og = gate_sm[3][tid];
            int colw = (int)rank * COLS_PER + tid;
            float cnew = fmaf(fg, cbuf[p][colw], ig * gg);
            float hnew = og * tanh_acc(cnew);
            hn[tid] = hnew; cn[tid] = cnew;
            out[((size_t)b * TT + t) * DD + colw] = hnew;
            uint32_t lah = s2u(&hbuf[p ^ 1][colw]);
            uint32_t lac = s2u(&cbuf[p ^ 1][colw]);
            #pragma unroll
            for (int rr = 0; rr < CL; rr++) { st_rank(lah, (uint32_t)rr, hnew); st_rank(lac, (uint32_t)rr, cnew); }
        }
        __syncthreads();
        // next-step q partial from this CTA's h-slice
        if (tid < DD) {
            float acc = 0.0f;
            #pragma unroll
            for (int k = 0; k < COLS_PER; k++) acc = fmaf(hn[k], Wa_s[k][tid], acc);
            uint32_t la = s2u(&qpart[rank][tid]);
            #pragma unroll
            for (int rr = 0; rr < CL; rr++) st_rank(la, (uint32_t)rr, acc);
        }
    }
}

// ---------------------------------------------------------------- launch
extern "C" void kernel_launch(void* const* d_in, const int* in_sizes, int n_in,
                              void* d_out, int out_size) {
    (void)in_sizes; (void)n_in; (void)out_size;
    const float* x    = (const float*)d_in[0];
    const float* H    = (const float*)d_in[1];
    const float* init = (const float*)d_in[2];
    const float* Wa   = (const float*)d_in[3];
    const float* Ua   = (const float*)d_in[4];
    const float* v    = (const float*)d_in[5];
    const float* Wi   = (const float*)d_in[6];
    const float* Ui   = (const float*)d_in[7];
    const float* Ci   = (const float*)d_in[8];
    const float* bi   = (const float*)d_in[9];
    const float* Wf   = (const float*)d_in[10];
    const float* Uf   = (const float*)d_in[11];
    const float* Cf   = (const float*)d_in[12];
    const float* bf   = (const float*)d_in[13];
    const float* Wc   = (const float*)d_in[14];
    const float* Uc   = (const float*)d_in[15];
    const float* Cc   = (const float*)d_in[16];
    const float* bc   = (const float*)d_in[17];
    const float* Wo   = (const float*)d_in[18];
    const float* Uo   = (const float*)d_in[19];
    const float* Co   = (const float*)d_in[20];
    const float* bo   = (const float*)d_in[21];
    float* out = (float*)d_out;

    hu_kernel<<<(BB * SS) / 8, DD>>>(H, Ua);
    xw_kernel<<<(BB * TT) / 8, DD>>>(x, Wi, Wf, Wc, Wo, bi, bf, bc, bo);
    attn_lstm_kernel<<<dim3(CL, BB), NTH>>>(H, init, Wa, v,
                                            Ui, Uf, Uc, Uo, Ci, Cf, Cc, Co, out);
}

// round 14
// speedup vs baseline: 1.4632x; 1.0130x over previous
#include <cuda_runtime.h>
#include <cstdint>
#include <cstddef>

#define BB 8
#define TT 128
#define SS 512
#define DD 128
#define CL 8           // cluster size (CTAs per batch)
#define ROWS 64        // SS/CL encoder rows per CTA
#define NTH 512
#define COLS_PER 16    // DD/CL output columns per CTA

// scratch (static device globals -- no allocation)
__device__ float g_HU[BB * SS * DD];          // H @ Ua
__device__ float g_XW4[BB * TT * 4 * DD];     // x @ {Wi,Wf,Wc,Wo} + bias

// ---------------------------------------------------------------- helpers
__device__ __forceinline__ uint32_t s2u(const void* p) {
    uint32_t a;
    asm("{ .reg .u64 t; cvta.to.shared.u64 t, %1; cvt.u32.u64 %0, t; }"
        : "=r"(a) : "l"(p));
    return a;
}
__device__ __forceinline__ void st_rank(uint32_t laddr, uint32_t rank, float v) {
    uint32_t r;
    asm("mapa.shared::cluster.u32 %0, %1, %2;" : "=r"(r) : "r"(laddr), "r"(rank));
    asm volatile("st.shared::cluster.f32 [%0], %1;" :: "r"(r), "f"(v) : "memory");
}
#define CLUSTER_SYNC() do { \
    asm volatile("barrier.cluster.arrive.aligned;" ::: "memory"); \
    asm volatile("barrier.cluster.wait.aligned;"   ::: "memory"); \
} while (0)

// MUFU tanh for the attention score path (feeds softmax weights only;
// measured rel_err impact: none). Runs on the otherwise-idle MUFU pipe.
__device__ __forceinline__ float tanh_mufu(float x) {
    float y;
    asm("tanh.approx.f32 %0, %1;" : "=f"(y) : "f"(x));
    return y;
}
// accurate activations for the LSTM gates (recurrent state path)
__device__ __forceinline__ float sigmoid_acc(float x) {
    return __fdividef(1.0f, 1.0f + __expf(-x));
}
__device__ __forceinline__ float tanh_acc(float x) {
    float e = __expf(2.0f * x);
    return __fdividef(e - 1.0f, e + 1.0f);
}

// ---------------------------------------------------------------- precompute
// HU[b,s,:] = H[b,s,:] @ Ua      (8 rows per block)
__global__ void __launch_bounds__(DD) hu_kernel(const float* __restrict__ Hm,
                                                const float* __restrict__ Ua) {
    __shared__ float hrow[8][DD];
    int r0 = blockIdx.x * 8;
    int d = threadIdx.x;
    #pragma unroll
    for (int i = 0; i < 8; i++) hrow[i][d] = Hm[(size_t)(r0 + i) * DD + d];
    __syncthreads();
    float acc[8];
    #pragma unroll
    for (int i = 0; i < 8; i++) acc[i] = 0.0f;
    #pragma unroll 4
    for (int k = 0; k < DD; k++) {
        float u = Ua[k * DD + d];
        #pragma unroll
        for (int i = 0; i < 8; i++) acc[i] = fmaf(hrow[i][k], u, acc[i]);
    }
    #pragma unroll
    for (int i = 0; i < 8; i++) g_HU[(size_t)(r0 + i) * DD + d] = acc[i];
}

// XW4[row,g,:] = x[row,:] @ W_g + b_g   (8 rows per block)
__global__ void __launch_bounds__(DD) xw_kernel(const float* __restrict__ x,
    const float* __restrict__ Wi_, const float* __restrict__ Wf_,
    const float* __restrict__ Wc_, const float* __restrict__ Wo_,
    const float* __restrict__ bi_, const float* __restrict__ bf_,
    const float* __restrict__ bc_, const float* __restrict__ bo_) {
    __shared__ float xr[8][DD];
    int r0 = blockIdx.x * 8;
    int d = threadIdx.x;
    #pragma unroll
    for (int i = 0; i < 8; i++) xr[i][d] = x[(size_t)(r0 + i) * DD + d];
    __syncthreads();
    const float* Ws[4] = {Wi_, Wf_, Wc_, Wo_};
    const float* bs[4] = {bi_, bf_, bc_, bo_};
    #pragma unroll
    for (int g = 0; g < 4; g++) {
        float bb = bs[g][d];
        float acc[8];
        #pragma unroll
        for (int i = 0; i < 8; i++) acc[i] = bb;
        #pragma unroll 4
        for (int k = 0; k < DD; k++) {
            float w = Ws[g][k * DD + d];
            #pragma unroll
            for (int i = 0; i < 8; i++) acc[i] = fmaf(xr[i][k], w, acc[i]);
        }
        #pragma unroll
        for (int i = 0; i < 8; i++)
            g_XW4[(((size_t)(r0 + i)) * 4 + g) * DD + d] = acc[i];
    }
}

// ---------------------------------------------------------------- main persistent kernel
// grid (CL, BB): cluster of CL CTAs along x per batch (blockIdx.y).
__global__ void __launch_bounds__(NTH, 1) __cluster_dims__(CL, 1, 1)
attn_lstm_kernel(const float* __restrict__ H, const float* __restrict__ init_states,
                 const float* __restrict__ Wa, const float* __restrict__ v,
                 const float* __restrict__ Ui, const float* __restrict__ Uf,
                 const float* __restrict__ Uc, const float* __restrict__ Uo,
                 const float* __restrict__ Ci, const float* __restrict__ Cf,
                 const float* __restrict__ Cc, const float* __restrict__ Co,
                 float* __restrict__ out)
{
    __shared__ float Wa_s[COLS_PER][DD];     // Wa rows [16r, 16r+16)
    __shared__ float v_s[DD];
    __shared__ float hbuf[2][DD];
    __shared__ float2 qv2_s[DD];             // (q[d], v[d]) pairs for phase 2
    __shared__ float qpart[CL][DD];
    __shared__ float2 hc_s[DD];              // (h[k], ctx[k]) pairs for phase 3
    __shared__ float ctxpart[CL][DD + 4];    // [.., DD] = partial exp-sum
    __shared__ float wred[16][DD];
    __shared__ float wsum[16];
    __shared__ float gate_sm[4][COLS_PER];
    __shared__ float hn[COLS_PER];

    const int tid  = threadIdx.x;
    const int b    = blockIdx.y;
    uint32_t rank;
    asm("mov.u32 %0, %%cluster_ctarank;" : "=r"(rank));
    const int j    = tid & 7;
    const int sl   = tid >> 3;           // row-local (phase2) / pair index (phase3)
    const int warp = tid >> 5;
    const int lane = tid & 31;

    const int g   = sl >> 4;             // gate 0..3  (i, f, c~, o)
    const int cl_ = sl & 15;             // local column
    const int col = (int)rank * COLS_PER + cl_;

    // ---- persistent register tiles ----
    float HUr[16], Hr[16], Ur[16], Cr[16];
    {
        const int srow = (int)rank * ROWS + sl;
        const float* hu = g_HU + ((size_t)b * SS + srow) * DD;
        const float* hp = H    + ((size_t)b * SS + srow) * DD;
        #pragma unroll
        for (int m = 0; m < 16; m++) { int d = j + 8 * m; HUr[m] = hu[d]; Hr[m] = hp[d]; }
        const float* Ug = (g == 0) ? Ui : (g == 1) ? Uf : (g == 2) ? Uc : Uo;
        const float* Cg = (g == 0) ? Ci : (g == 1) ? Cf : (g == 2) ? Cc : Co;
        #pragma unroll
        for (int m = 0; m < 16; m++) { int k = j + 8 * m; Ur[m] = Ug[k * DD + col]; Cr[m] = Cg[k * DD + col]; }
    }
    // c state is private to its owning thread: register, never broadcast
    float creg = (tid < COLS_PER)
               ? init_states[(BB + b) * DD + (int)rank * COLS_PER + tid] : 0.0f;

    // ---- smem init ----
    for (int i = tid; i < COLS_PER * DD; i += NTH) {
        int kr = i >> 7, dd = i & 127;
        Wa_s[kr][dd] = Wa[((int)rank * COLS_PER + kr) * DD + dd];
    }
    float vreg = 0.0f;
    if (tid < DD) {
        vreg         = v[tid];
        v_s[tid]     = vreg;
        hbuf[0][tid] = init_states[b * DD + tid];
        hbuf[1][tid] = 0.0f;
    }
    __syncthreads();
    // initial q partial from h0's k-slice, broadcast to all CTAs (incl. self)
    if (tid < DD) {
        float acc = 0.0f;
        #pragma unroll
        for (int k = 0; k < COLS_PER; k++)
            acc = fmaf(hbuf[0][(int)rank * COLS_PER + k], Wa_s[k][tid], acc);
        uint32_t la = s2u(&qpart[rank][tid]);
        #pragma unroll
        for (int rr = 0; rr < CL; rr++) st_rank(la, (uint32_t)rr, acc);
    }

    const float* xw_base = g_XW4 + (size_t)b * TT * 4 * DD;

    for (int t = 0; t < TT; t++) {
        const int p = t & 1;
        CLUSTER_SYNC();                      // qpart + hbuf[p] from all peers visible

        // prefetch the x@W gate term (L2 latency hidden behind phase 2)
        float xwv = (j == 0) ? xw_base[((size_t)t * 4 + g) * DD + col] : 0.0f;

        // ---- build full q, fused with v into float2 pairs ----
        if (tid < DD) {
            float acc = qpart[0][tid];
            #pragma unroll
            for (int rr = 1; rr < CL; rr++) acc += qpart[rr][tid];
            qv2_s[tid] = make_float2(acc, vreg);
        }
        __syncthreads();

        // ---- phase 2: scores + exp + local context partial for 64 rows ----
        {
            float acc = 0.0f;
            #pragma unroll
            for (int m = 0; m < 16; m++) {
                float2 qv = qv2_s[j + 8 * m];      // one LDS.64: (q, v)
                acc = fmaf(tanh_mufu(HUr[m] + qv.x), qv.y, acc);
            }
            acc += __shfl_xor_sync(0xffffffffu, acc, 1);
            acc += __shfl_xor_sync(0xffffffffu, acc, 2);
            acc += __shfl_xor_sync(0xffffffffu, acc, 4);
            float e = __expf(acc);           // scores are tiny; no max-shift needed
            float cp[16];
            #pragma unroll
            for (int m = 0; m < 16; m++) cp[m] = e * Hr[m];
            #pragma unroll
            for (int m = 0; m < 16; m++) {   // reduce over the 4 rows in this warp
                cp[m] += __shfl_xor_sync(0xffffffffu, cp[m], 8);
                cp[m] += __shfl_xor_sync(0xffffffffu, cp[m], 16);
            }
            float es = e + __shfl_xor_sync(0xffffffffu, e, 8);
            es += __shfl_xor_sync(0xffffffffu, es, 16);
            if (lane < 8) {
                #pragma unroll
                for (int m = 0; m < 16; m++) wred[warp][lane + 8 * m] = cp[m];
                if (lane == 0) wsum[warp] = es;
            }
        }
        __syncthreads();
        // local reduce over 16 warps, broadcast (ctx partial + exp-sum) to all CTAs
        if (tid < DD) {
            float acc = wred[0][tid];
            #pragma unroll
            for (int w = 1; w < 16; w++) acc += wred[w][tid];
            uint32_t la = s2u(&ctxpart[rank][tid]);
            #pragma unroll
            for (int rr = 0; rr < CL; rr++) st_rank(la, (uint32_t)rr, acc);
            if (tid == 0) {
                float es = wsum[0];
                #pragma unroll
                for (int w = 1; w < 16; w++) es += wsum[w];
                uint32_t lb = s2u(&ctxpart[rank][DD]);
                #pragma unroll
                for (int rr = 0; rr < CL; rr++) st_rank(lb, (uint32_t)rr, es);
            }
        }
        CLUSTER_SYNC();                      // ctx partials from all peers visible

        // ---- phase 3: full context fused with h into float2 pairs ----
        if (tid < DD) {
            float acc = ctxpart[0][tid];
            float es  = ctxpart[0][DD];
            #pragma unroll
            for (int rr = 1; rr < CL; rr++) { acc += ctxpart[rr][tid]; es += ctxpart[rr][DD]; }
            hc_s[tid] = make_float2(hbuf[p][tid], acc * __fdividef(1.0f, es));
        }
        __syncthreads();
        {
            float acc = 0.0f;
            #pragma unroll
            for (int m = 0; m < 16; m++) {
                float2 hc = hc_s[j + 8 * m];       // one LDS.64: (h, ctx)
                acc = fmaf(hc.x, Ur[m], acc);
                acc = fmaf(hc.y, Cr[m], acc);
            }
            acc += __shfl_xor_sync(0xffffffffu, acc, 1);
            acc += __shfl_xor_sync(0xffffffffu, acc, 2);
            acc += __shfl_xor_sync(0xffffffffu, acc, 4);
            if (j == 0) {
                float pre = acc + xwv;
                gate_sm[g][cl_] = (g == 2) ? tanh_acc(pre) : sigmoid_acc(pre);
            }
        }
        __syncthreads();
        if (tid < COLS_PER) {
            float ig = gate_sm[0][tid], fg = gate_sm[1][tid];
            float gg = gate_sm[2][tid], og = gate_sm[3][tid];
            int colw = (int)rank * COLS_PER + tid;
            float cnew = fmaf(fg, creg, ig * gg);
            creg = cnew;
            float hnew = og * tanh_acc(cnew);
            hn[tid] = hnew;
            out[((size_t)b * TT + t) * DD + colw] = hnew;
            if (t < TT - 1) {
                uint32_t lah = s2u(&hbuf[p ^ 1][colw]);
                #pragma unroll
                for (int rr = 0; rr < CL; rr++) st_rank(lah, (uint32_t)rr, hnew);
            }
        }
        __syncthreads();
        // next-step q partial from this CTA's h-slice
        if (tid < DD && t < TT - 1) {
            float acc = 0.0f;
            #pragma unroll
            for (int k = 0; k < COLS_PER; k++) acc = fmaf(hn[k], Wa_s[k][tid], acc);
            uint32_t la = s2u(&qpart[rank][tid]);
            #pragma unroll
            for (int rr = 0; rr < CL; rr++) st_rank(la, (uint32_t)rr, acc);
        }
    }
}

// ---------------------------------------------------------------- launch
extern "C" void kernel_launch(void* const* d_in, const int* in_sizes, int n_in,
                              void* d_out, int out_size) {
    (void)in_sizes; (void)n_in; (void)out_size;
    const float* x    = (const float*)d_in[0];
    const float* H    = (const float*)d_in[1];
    const float* init = (const float*)d_in[2];
    const float* Wa   = (const float*)d_in[3];
    const float* Ua   = (const float*)d_in[4];
    const float* v    = (const float*)d_in[5];
    const float* Wi   = (const float*)d_in[6];
    const float* Ui   = (const float*)d_in[7];
    const float* Ci   = (const float*)d_in[8];
    const float* bi   = (const float*)d_in[9];
    const float* Wf   = (const float*)d_in[10];
    const float* Uf   = (const float*)d_in[11];
    const float* Cf   = (const float*)d_in[12];
    const float* bf   = (const float*)d_in[13];
    const float* Wc   = (const float*)d_in[14];
    const float* Uc   = (const float*)d_in[15];
    const float* Cc   = (const float*)d_in[16];
    const float* bc   = (const float*)d_in[17];
    const float* Wo   = (const float*)d_in[18];
    const float* Uo   = (const float*)d_in[19];
    const float* Co   = (const float*)d_in[20];
    const float* bo   = (const float*)d_in[21];
    float* out = (float*)d_out;

    hu_kernel<<<(BB * SS) / 8, DD>>>(H, Ua);
    xw_kernel<<<(BB * TT) / 8, DD>>>(x, Wi, Wf, Wc, Wo, bi, bf, bc, bo);
    attn_lstm_kernel<<<dim3(CL, BB), NTH>>>(H, init, Wa, v,
                                            Ui, Uf, Uc, Uo, Ci, Cf, Cc, Co, out);
}